// round 3
// baseline (speedup 1.0000x reference)
#include <cuda_runtime.h>
#include <cuda_bf16.h>

// MLPDecoder: logit[e] = relu([zu, zv, |zu-zv|] @ W1 + b1) @ W2 + b2
// Split: feat@W1 = zu@W1a + zv@W1b + |zu-zv|@W1c
// Kernel1: AB[n] = [ z[n]@W1a , z[n]@W1b ]  (register-blocked GEMM, 64x256 tile)
// Kernel2: per 128-edge tile: C = |zu-zv| @ W1c (register-blocked 128x128), then
//          h = relu(C + ABu + ABv + b1); out = h @ W2 + b2.
// fp32x2 packed FMA (fma.rn.f32x2) throughout. edge_index is int32 on the wire.

#define DIM 128
#define HID 128
#define N_NODES_MAX 100000

__device__ float g_AB[(size_t)N_NODES_MAX * 256];

typedef unsigned long long ull;

__device__ __forceinline__ ull pack2(float lo, float hi) {
    ull r;
    asm("mov.b64 %0, {%1, %2};" : "=l"(r) : "f"(lo), "f"(hi));
    return r;
}
__device__ __forceinline__ void unpack2(ull v, float& lo, float& hi) {
    asm("mov.b64 {%0, %1}, %2;" : "=f"(lo), "=f"(hi) : "l"(v));
}
__device__ __forceinline__ ull fma2(ull a, ull b, ull c) {
    ull d;
    asm("fma.rn.f32x2 %0, %1, %2, %3;" : "=l"(d) : "l"(a), "l"(b), "l"(c));
    return d;
}

// ---------------------------------------------------------------------------
// Kernel 1: AB = z @ [W1a | W1b].  Tile 64 rows x 256 cols, K=128.
// 256 threads: tx = tid&31 (8 j each -> 256), ty = tid>>5 (8 rows each -> 64).
// SMEM: sB [128][256] = 128KB, sA [128][68] (k-major z tile, padded) = 34KB.
// ---------------------------------------------------------------------------
__global__ __launch_bounds__(256, 1) void precompute_ab_kernel(
    const float* __restrict__ z, const float* __restrict__ W1,
    float* __restrict__ AB, int N)
{
    extern __shared__ __align__(16) unsigned char smem_raw[];
    float* sB = (float*)smem_raw;                 // [128][256]
    float* sA = sB + 128 * 256;                   // [128][68]

    const int tid = threadIdx.x;
    const int tx = tid & 31;
    const int ty = tid >> 5;
    const int rowBase = blockIdx.x * 64;

    // Wab[k][j]: j<128 -> W1a[k][j]; j>=128 -> W1b[k][j-128]
    for (int i = tid; i < 128 * 256; i += 256) {
        int k = i >> 8, j = i & 255;
        sB[i] = (j < 128) ? W1[k * 128 + j] : W1[(128 + k) * 128 + (j - 128)];
    }
    // z tile, transposed to k-major. r = row within tile, qh = k-quarter.
    {
        int r  = tid & 63;
        int qh = tid >> 6;          // 0..3 -> k 32*qh .. 32*qh+31
        int row = rowBase + r;
        if (row >= N) row = N - 1;  // clamp; writes guarded later
        const float4* zr = (const float4*)(z + row * DIM) + qh * 8;
        #pragma unroll
        for (int c = 0; c < 8; c++) {
            float4 a = zr[c];
            int k0 = qh * 32 + c * 4;
            sA[(k0 + 0) * 68 + r] = a.x;
            sA[(k0 + 1) * 68 + r] = a.y;
            sA[(k0 + 2) * 68 + r] = a.z;
            sA[(k0 + 3) * 68 + r] = a.w;
        }
    }
    __syncthreads();

    ull acc[8][4];
    #pragma unroll
    for (int i = 0; i < 8; i++)
        #pragma unroll
        for (int p = 0; p < 4; p++) acc[i][p] = 0ull;

    #pragma unroll 8
    for (int k = 0; k < 128; k++) {
        const float* bp = sB + k * 256 + tx * 8;
        ulonglong2 w0 = *(const ulonglong2*)bp;
        ulonglong2 w1 = *(const ulonglong2*)(bp + 4);
        const float* ap = sA + k * 68 + ty * 8;
        float4 a0 = *(const float4*)ap;
        float4 a1 = *(const float4*)(ap + 4);
        ull a2[8];
        a2[0] = pack2(a0.x, a0.x); a2[1] = pack2(a0.y, a0.y);
        a2[2] = pack2(a0.z, a0.z); a2[3] = pack2(a0.w, a0.w);
        a2[4] = pack2(a1.x, a1.x); a2[5] = pack2(a1.y, a1.y);
        a2[6] = pack2(a1.z, a1.z); a2[7] = pack2(a1.w, a1.w);
        #pragma unroll
        for (int i = 0; i < 8; i++) {
            acc[i][0] = fma2(a2[i], w0.x, acc[i][0]);
            acc[i][1] = fma2(a2[i], w0.y, acc[i][1]);
            acc[i][2] = fma2(a2[i], w1.x, acc[i][2]);
            acc[i][3] = fma2(a2[i], w1.y, acc[i][3]);
        }
    }

    #pragma unroll
    for (int i = 0; i < 8; i++) {
        int row = rowBase + ty * 8 + i;
        if (row < N) {
            float4 lo, hi;
            unpack2(acc[i][0], lo.x, lo.y); unpack2(acc[i][1], lo.z, lo.w);
            unpack2(acc[i][2], hi.x, hi.y); unpack2(acc[i][3], hi.z, hi.w);
            *(float4*)(AB + (size_t)row * 256 + tx * 8)     = lo;
            *(float4*)(AB + (size_t)row * 256 + tx * 8 + 4) = hi;
        }
    }
}

// ---------------------------------------------------------------------------
// Kernel 2: per 128-edge tile, C = diff @ W1c, fused epilogue.
// 256 threads: tx = tid&15 (8 j each -> 128), ty = tid>>4 (8 edges each -> 128).
// SMEM: sA diffs k-major [128][132] 67.5KB, sB W1c [128][128] 64KB,
//       sS = ABu+ABv+b1 edge-major [128][128] 64KB, sP partials [128][16] 8KB.
// ---------------------------------------------------------------------------
__global__ __launch_bounds__(256, 1) void edge_mlp_kernel(
    const float* __restrict__ z, const int* __restrict__ eidx,
    const float* __restrict__ W1, const float* __restrict__ b1,
    const float* __restrict__ W2, const float* __restrict__ b2,
    const float* __restrict__ AB, float* __restrict__ out, int E)
{
    extern __shared__ __align__(16) unsigned char smem_raw[];
    float* sA = (float*)smem_raw;        // [128][132]
    float* sB = sA + 128 * 132;          // [128][128]
    float* sS = sB + 128 * 128;          // [128][128]
    float* sP = sS + 128 * 128;          // [128][16]

    const int tid = threadIdx.x;
    const int tx = tid & 15;
    const int ty = tid >> 4;
    const int eBase = blockIdx.x * 128;

    // W1c -> sB (contiguous rows 256..384 of W1 start at float 32768)
    {
        const float4* src = (const float4*)(W1 + 32768);
        float4* dst = (float4*)sB;
        for (int i = tid; i < 4096; i += 256) dst[i] = src[i];
    }
    // gather: diffs (k-major, padded) + S = ABu + ABv + b1 (edge-major)
    {
        int e = tid & 127;
        int half = tid >> 7;             // 0/1 -> k 0..63 / 64..127
        int ge = eBase + e;
        int u = (ge < E) ? eidx[ge] : 0;
        int v = (ge < E) ? eidx[E + ge] : 0;
        const float4* zu4 = (const float4*)(z + (size_t)u * DIM) + half * 16;
        const float4* zv4 = (const float4*)(z + (size_t)v * DIM) + half * 16;
        const float4* au4 = (const float4*)(AB + (size_t)u * 256) + half * 16;
        const float4* bv4 = (const float4*)(AB + (size_t)v * 256 + 128) + half * 16;
        const float4* b14 = (const float4*)b1 + half * 16;
        #pragma unroll
        for (int c = 0; c < 16; c++) {
            float4 a = __ldg(zu4 + c);
            float4 b = __ldg(zv4 + c);
            int k0 = half * 64 + c * 4;
            sA[(k0 + 0) * 132 + e] = fabsf(a.x - b.x);
            sA[(k0 + 1) * 132 + e] = fabsf(a.y - b.y);
            sA[(k0 + 2) * 132 + e] = fabsf(a.z - b.z);
            sA[(k0 + 3) * 132 + e] = fabsf(a.w - b.w);
            float4 p = __ldg(au4 + c);
            float4 q = __ldg(bv4 + c);
            float4 r = __ldg(b14 + c);
            float4 s;
            s.x = p.x + q.x + r.x; s.y = p.y + q.y + r.y;
            s.z = p.z + q.z + r.z; s.w = p.w + q.w + r.w;
            *(float4*)(sS + e * 128 + k0) = s;
        }
    }
    float4 w2a = __ldg((const float4*)W2 + tx * 2);
    float4 w2b = __ldg((const float4*)W2 + tx * 2 + 1);
    __syncthreads();

    ull acc[8][4];
    #pragma unroll
    for (int i = 0; i < 8; i++)
        #pragma unroll
        for (int p = 0; p < 4; p++) acc[i][p] = 0ull;

    #pragma unroll 8
    for (int k = 0; k < 128; k++) {
        const float* bp = sB + k * 128 + tx * 8;
        ulonglong2 w0 = *(const ulonglong2*)bp;
        ulonglong2 w1 = *(const ulonglong2*)(bp + 4);
        const float* ap = sA + k * 132 + ty * 8;
        float4 a0 = *(const float4*)ap;
        float4 a1 = *(const float4*)(ap + 4);
        ull a2[8];
        a2[0] = pack2(a0.x, a0.x); a2[1] = pack2(a0.y, a0.y);
        a2[2] = pack2(a0.z, a0.z); a2[3] = pack2(a0.w, a0.w);
        a2[4] = pack2(a1.x, a1.x); a2[5] = pack2(a1.y, a1.y);
        a2[6] = pack2(a1.z, a1.z); a2[7] = pack2(a1.w, a1.w);
        #pragma unroll
        for (int i = 0; i < 8; i++) {
            acc[i][0] = fma2(a2[i], w0.x, acc[i][0]);
            acc[i][1] = fma2(a2[i], w0.y, acc[i][1]);
            acc[i][2] = fma2(a2[i], w1.x, acc[i][2]);
            acc[i][3] = fma2(a2[i], w1.y, acc[i][3]);
        }
    }

    // epilogue: h = relu(C + S); partial = h . W2 over this thread's 8 j's
    #pragma unroll
    for (int i = 0; i < 8; i++) {
        int e = ty * 8 + i;
        const float* sp = sS + e * 128 + tx * 8;
        float4 s0 = *(const float4*)sp;
        float4 s1 = *(const float4*)(sp + 4);
        float c0, c1, c2, c3, c4, c5, c6, c7;
        unpack2(acc[i][0], c0, c1); unpack2(acc[i][1], c2, c3);
        unpack2(acc[i][2], c4, c5); unpack2(acc[i][3], c6, c7);
        float ps;
        ps  = fmaxf(c0 + s0.x, 0.f) * w2a.x;
        ps += fmaxf(c1 + s0.y, 0.f) * w2a.y;
        ps += fmaxf(c2 + s0.z, 0.f) * w2a.z;
        ps += fmaxf(c3 + s0.w, 0.f) * w2a.w;
        ps += fmaxf(c4 + s1.x, 0.f) * w2b.x;
        ps += fmaxf(c5 + s1.y, 0.f) * w2b.y;
        ps += fmaxf(c6 + s1.z, 0.f) * w2b.z;
        ps += fmaxf(c7 + s1.w, 0.f) * w2b.w;
        sP[e * 16 + tx] = ps;
    }
    __syncthreads();

    if (tid < 128) {
        int ge = eBase + tid;
        const float4* pp = (const float4*)(sP + tid * 16);
        float4 p0 = pp[0], p1 = pp[1], p2 = pp[2], p3 = pp[3];
        float s = ((p0.x + p0.y) + (p0.z + p0.w)) + ((p1.x + p1.y) + (p1.z + p1.w))
                + ((p2.x + p2.y) + (p2.z + p2.w)) + ((p3.x + p3.y) + (p3.z + p3.w));
        if (ge < E) out[ge] = s + b2[0];
    }
}

extern "C" void kernel_launch(void* const* d_in, const int* in_sizes, int n_in,
                              void* d_out, int out_size) {
    const float* z    = (const float*)d_in[0];
    const int*   eidx = (const int*)d_in[1];     // int32 on the wire (JAX x64 off)
    const float* W1   = (const float*)d_in[2];
    const float* b1   = (const float*)d_in[3];
    const float* W2   = (const float*)d_in[4];
    const float* b2   = (const float*)d_in[5];
    float*       out  = (float*)d_out;

    const int N = in_sizes[0] / DIM;       // 100000
    const int E = in_sizes[1] / 2;         // 500000

    float* AB = nullptr;
    cudaGetSymbolAddress((void**)&AB, g_AB);

    const int k1_smem = (128 * 256 + 128 * 68) * 4;                    // 165888
    const int k2_smem = (128 * 132 + 128 * 128 + 128 * 128 + 128 * 16) * 4; // 206848
    cudaFuncSetAttribute(precompute_ab_kernel, cudaFuncAttributeMaxDynamicSharedMemorySize, k1_smem);
    cudaFuncSetAttribute(edge_mlp_kernel,      cudaFuncAttributeMaxDynamicSharedMemorySize, k2_smem);

    const int g1 = (N + 63) / 64;          // 1563
    const int g2 = (E + 127) / 128;        // 3907
    precompute_ab_kernel<<<g1, 256, k1_smem>>>(z, W1, AB, N);
    edge_mlp_kernel<<<g2, 256, k2_smem>>>(z, eidx, W1, b1, W2, b2, AB, out, E);
}

// round 4
// speedup vs baseline: 1.6885x; 1.6885x over previous
#include <cuda_runtime.h>
#include <cstdint>

// MLPDecoder via tf32 tensor-core mma.sync:
// logit[e] = relu([zu, zv, |zu-zv|] @ W1 + b1) @ W2 + b2
// One fused kernel. Per block: 128 edges x 128 hid, K=384 processed as three
// 128-wide chunks (zu / zv / |zu-zv|), feat+W chunks staged in smem (tf32).
// edge_index is int32 on the wire (JAX x64 disabled).

#define DIM 128
#define HID 128
#define EPB 128                 // edges per block
#define FSTRIDE 132             // smem row stride (floats), conflict-free frags

__device__ __forceinline__ uint32_t f2tf(float x) {
    uint32_t r; asm("cvt.rna.tf32.f32 %0, %1;" : "=r"(r) : "f"(x)); return r;
}
__device__ __forceinline__ float tfpack(float x) {  // tf32 bits in a float container
    return __uint_as_float(f2tf(x));
}
__device__ __forceinline__ void mma_tf32(
    float& c0, float& c1, float& c2, float& c3,
    uint32_t a0, uint32_t a1, uint32_t a2, uint32_t a3,
    uint32_t b0, uint32_t b1)
{
    asm volatile(
        "mma.sync.aligned.m16n8k8.row.col.f32.tf32.tf32.f32 "
        "{%0,%1,%2,%3}, {%4,%5,%6,%7}, {%8,%9}, {%0,%1,%2,%3};"
        : "+f"(c0), "+f"(c1), "+f"(c2), "+f"(c3)
        : "r"(a0), "r"(a1), "r"(a2), "r"(a3), "r"(b0), "r"(b1));
}

__global__ __launch_bounds__(256, 1) void edge_mlp_tc(
    const float* __restrict__ z, const int* __restrict__ eidx,
    const float* __restrict__ W1, const float* __restrict__ b1,
    const float* __restrict__ W2, const float* __restrict__ b2,
    float* __restrict__ out, int E)
{
    extern __shared__ __align__(16) unsigned char smem_raw[];
    float* sF  = (float*)smem_raw;            // feat chunk [128 e][FSTRIDE]
    float* sW  = sF + 128 * FSTRIDE;          // W chunk    [128 k][FSTRIDE]
    float* sP  = sW + 128 * FSTRIDE;          // partials   [128][2]
    float* sb1 = sP + 256;                    // 128
    float* sw2 = sb1 + 128;                   // 128

    const int tid  = threadIdx.x;
    const int warp = tid >> 5;
    const int lane = tid & 31;
    const int gid  = lane >> 2;   // 0..7
    const int tig  = lane & 3;    // 0..3
    const int wx   = warp & 1;    // n-half (64 cols)
    const int wy   = warp >> 1;   // 0..3 (32 edges)
    const int eBase = blockIdx.x * EPB;

    if (tid < 128) { sb1[tid] = b1[tid]; sw2[tid] = W2[tid]; }

    // gather assignment: e = tid>>1, half = tid&1 (64 k each)
    const int e_g  = tid >> 1;
    const int half = tid & 1;
    const int ge_g = eBase + e_g;
    int u = 0, v = 0;
    if (ge_g < E) { u = eidx[ge_g]; v = eidx[E + ge_g]; }
    const float4* zu4 = (const float4*)(z + (size_t)u * DIM) + half * 16;
    const float4* zv4 = (const float4*)(z + (size_t)v * DIM) + half * 16;
    float* fdst = sF + e_g * FSTRIDE + half * 64;
    float* wdst = sW + e_g * FSTRIDE + half * 64;   // same indexing: row e_g of W chunk
    const int kOff = half * 64;

    float c[2][8][4];
    #pragma unroll
    for (int m = 0; m < 2; m++)
        #pragma unroll
        for (int n = 0; n < 8; n++)
            #pragma unroll
            for (int q = 0; q < 4; q++) c[m][n][q] = 0.f;

    const float* fBase = sF + (32 * wy) * FSTRIDE;
    const float* wBase = sW + 64 * wx;

    #pragma unroll 1
    for (int ch = 0; ch < 3; ch++) {
        __syncthreads();   // previous chunk's consumers done

        // stage W chunk: k rows [ch*128, ch*128+128), this thread does row e_g, half
        {
            const float4* wsrc = (const float4*)(W1 + ((size_t)(ch * 128 + e_g)) * HID) + half * 16;
            #pragma unroll
            for (int cc = 0; cc < 16; cc++) {
                float4 w = __ldg(wsrc + cc);
                float4 o;
                o.x = tfpack(w.x); o.y = tfpack(w.y);
                o.z = tfpack(w.z); o.w = tfpack(w.w);
                *(float4*)(wdst + cc * 4) = o;
            }
        }
        // build feat chunk
        if (ch == 0) {
            #pragma unroll
            for (int cc = 0; cc < 16; cc++) {
                float4 a = __ldg(zu4 + cc);
                float4 o;
                o.x = tfpack(a.x); o.y = tfpack(a.y);
                o.z = tfpack(a.z); o.w = tfpack(a.w);
                *(float4*)(fdst + cc * 4) = o;
            }
        } else if (ch == 1) {
            #pragma unroll
            for (int cc = 0; cc < 16; cc++) {
                float4 a = __ldg(zv4 + cc);
                float4 o;
                o.x = tfpack(a.x); o.y = tfpack(a.y);
                o.z = tfpack(a.z); o.w = tfpack(a.w);
                *(float4*)(fdst + cc * 4) = o;
            }
        } else {
            #pragma unroll
            for (int cc = 0; cc < 16; cc++) {
                float4 a = __ldg(zu4 + cc);
                float4 b = __ldg(zv4 + cc);
                float4 o;
                o.x = tfpack(fabsf(a.x - b.x)); o.y = tfpack(fabsf(a.y - b.y));
                o.z = tfpack(fabsf(a.z - b.z)); o.w = tfpack(fabsf(a.w - b.w));
                *(float4*)(fdst + cc * 4) = o;
            }
        }
        (void)kOff;
        __syncthreads();   // chunk staged

        // 16 k-steps of m16n8k8
        #pragma unroll
        for (int ks = 0; ks < 16; ks++) {
            const int k0 = ks * 8;
            uint32_t a[2][4];
            #pragma unroll
            for (int mt = 0; mt < 2; mt++) {
                const float* ap = fBase + (16 * mt + gid) * FSTRIDE + k0 + tig;
                a[mt][0] = __float_as_uint(ap[0]);
                a[mt][1] = __float_as_uint(ap[8 * FSTRIDE]);
                a[mt][2] = __float_as_uint(ap[4]);
                a[mt][3] = __float_as_uint(ap[8 * FSTRIDE + 4]);
            }
            #pragma unroll
            for (int nt = 0; nt < 8; nt++) {
                const float* bp = wBase + (k0 + tig) * FSTRIDE + 8 * nt + gid;
                uint32_t b0 = __float_as_uint(bp[0]);
                uint32_t b1r = __float_as_uint(bp[4 * FSTRIDE]);
                mma_tf32(c[0][nt][0], c[0][nt][1], c[0][nt][2], c[0][nt][3],
                         a[0][0], a[0][1], a[0][2], a[0][3], b0, b1r);
                mma_tf32(c[1][nt][0], c[1][nt][1], c[1][nt][2], c[1][nt][3],
                         a[1][0], a[1][1], a[1][2], a[1][3], b0, b1r);
            }
        }
    }

    // epilogue: h = relu(C + b1); partial = h . W2; reduce quad -> smem -> out
    #pragma unroll
    for (int mt = 0; mt < 2; mt++) {
        float p1 = 0.f, p2 = 0.f;
        #pragma unroll
        for (int nt = 0; nt < 8; nt++) {
            int j = 64 * wx + 8 * nt + 2 * tig;
            float ba = sb1[j], bb = sb1[j + 1];
            float wa = sw2[j], wb = sw2[j + 1];
            p1 += fmaxf(c[mt][nt][0] + ba, 0.f) * wa + fmaxf(c[mt][nt][1] + bb, 0.f) * wb;
            p2 += fmaxf(c[mt][nt][2] + ba, 0.f) * wa + fmaxf(c[mt][nt][3] + bb, 0.f) * wb;
        }
        p1 += __shfl_xor_sync(0xFFFFFFFFu, p1, 1);
        p1 += __shfl_xor_sync(0xFFFFFFFFu, p1, 2);
        p2 += __shfl_xor_sync(0xFFFFFFFFu, p2, 1);
        p2 += __shfl_xor_sync(0xFFFFFFFFu, p2, 2);
        if (tig == 0) {
            int r = 32 * wy + 16 * mt + gid;
            sP[r * 2 + wx] = p1;
            sP[(r + 8) * 2 + wx] = p2;
        }
    }
    __syncthreads();

    if (tid < 128) {
        int ge = eBase + tid;
        if (ge < E) out[ge] = sP[tid * 2 + 0] + sP[tid * 2 + 1] + b2[0];
    }
}

extern "C" void kernel_launch(void* const* d_in, const int* in_sizes, int n_in,
                              void* d_out, int out_size) {
    const float* z    = (const float*)d_in[0];
    const int*   eidx = (const int*)d_in[1];   // int32 on the wire
    const float* W1   = (const float*)d_in[2];
    const float* b1   = (const float*)d_in[3];
    const float* W2   = (const float*)d_in[4];
    const float* b2   = (const float*)d_in[5];
    float*       out  = (float*)d_out;

    const int E = in_sizes[1] / 2;   // 500000

    const int smem = (128 * FSTRIDE * 2 + 256 + 128 + 128) * 4;  // 137216 B
    cudaFuncSetAttribute(edge_mlp_tc, cudaFuncAttributeMaxDynamicSharedMemorySize, smem);

    const int grid = (E + EPB - 1) / EPB;   // 3907
    edge_mlp_tc<<<grid, 256, smem>>>(z, eidx, W1, b1, W2, b2, out, E);
}

// round 5
// speedup vs baseline: 2.4789x; 1.4682x over previous
#include <cuda_runtime.h>
#include <cstdint>

// MLPDecoder via tf32 mma.sync + ldmatrix fragments:
// logit[e] = relu([zu, zv, |zu-zv|] @ W1 + b1) @ W2 + b2
// Prep kernel: g_Wt[j][k] = tf32(W1[k][j])  (transpose once, 128x384).
// Main kernel: per block 128 edges x 128 hid; K=384 as six 64-wide chunks.
//   sF [128e][64k] and sW [128j][64k], both XOR-swizzled for conflict-free LDSM.
//   Fragments via ldmatrix.m8n8.x4; 2 CTAs/SM (<=128 regs, 66KB smem).
// edge_index is int32 on the wire (JAX x64 disabled).

#define DIM 128
#define HID 128
#define EPB 128

__device__ float g_Wt[128 * 384];   // [j][k], tf32-rounded

__device__ __forceinline__ uint32_t f2tf(float x) {
    uint32_t r; asm("cvt.rna.tf32.f32 %0, %1;" : "=r"(r) : "f"(x)); return r;
}
__device__ __forceinline__ float tfpack(float x) { return __uint_as_float(f2tf(x)); }
__device__ __forceinline__ float4 tf4(float4 a) {
    float4 o; o.x = tfpack(a.x); o.y = tfpack(a.y); o.z = tfpack(a.z); o.w = tfpack(a.w);
    return o;
}

__device__ __forceinline__ void ldsm4(uint32_t& r0, uint32_t& r1, uint32_t& r2, uint32_t& r3,
                                      uint32_t addr) {
    asm volatile("ldmatrix.sync.aligned.m8n8.x4.shared.b16 {%0,%1,%2,%3}, [%4];"
                 : "=r"(r0), "=r"(r1), "=r"(r2), "=r"(r3) : "r"(addr));
}

__device__ __forceinline__ void mma_tf32(
    float& c0, float& c1, float& c2, float& c3,
    uint32_t a0, uint32_t a1, uint32_t a2, uint32_t a3,
    uint32_t b0, uint32_t b1)
{
    asm volatile(
        "mma.sync.aligned.m16n8k8.row.col.f32.tf32.tf32.f32 "
        "{%0,%1,%2,%3}, {%4,%5,%6,%7}, {%8,%9}, {%0,%1,%2,%3};"
        : "+f"(c0), "+f"(c1), "+f"(c2), "+f"(c3)
        : "r"(a0), "r"(a1), "r"(a2), "r"(a3), "r"(b0), "r"(b1));
}

// ---------------------------------------------------------------------------
__global__ void prep_wt(const float* __restrict__ W1) {
    int i = blockIdx.x * 256 + threadIdx.x;          // over 384*128
    if (i < 384 * 128) {
        int k = i >> 7, j = i & 127;
        g_Wt[(size_t)j * 384 + k] = tfpack(W1[i]);   // coalesced read, scattered write
    }
}

// ---------------------------------------------------------------------------
__global__ __launch_bounds__(256, 2) void edge_mlp_tc(
    const float* __restrict__ z, const int* __restrict__ eidx,
    const float* __restrict__ b1, const float* __restrict__ W2,
    const float* __restrict__ b2, float* __restrict__ out, int E)
{
    extern __shared__ __align__(16) unsigned char smem_raw[];
    float* sF  = (float*)smem_raw;        // [128][64] swizzled (32KB)
    float* sW  = sF + 128 * 64;           // [128][64] swizzled (32KB)
    float* sP  = sW + 128 * 64;           // [128][2]
    float* sb1 = sP + 256;                // 128
    float* sw2 = sb1 + 128;               // 128

    const int tid  = threadIdx.x;
    const int warp = tid >> 5;
    const int lane = tid & 31;
    const int gid  = lane >> 2;
    const int tig  = lane & 3;
    const int wx   = warp & 1;            // n-half (64 cols)
    const int wy   = warp >> 1;           // 0..3  (32 edges)
    const int eBase = blockIdx.x * EPB;

    if (tid < 128) { sb1[tid] = b1[tid]; sw2[tid] = W2[tid]; }

    // gather assignment: e = tid>>1, half = tid&1 (32 k-floats each per chunk)
    const int e_g  = tid >> 1;
    const int half = tid & 1;
    const int ge_g = eBase + e_g;
    int u = 0, v = 0;
    if (ge_g < E) { u = eidx[ge_g]; v = eidx[E + ge_g]; }
    const float* zu = z + (size_t)u * DIM;
    const float* zv = z + (size_t)v * DIM;
    const int e7 = e_g & 7;
    char* fRow = (char*)sF + e_g * 256;

    // LDSM lane addressing
    const uint32_t sFb = (uint32_t)__cvta_generic_to_shared(sF);
    const uint32_t sWb = (uint32_t)__cvta_generic_to_shared(sW);
    const int l7    = lane & 7;
    const int roffA = ((lane >> 3) & 1) * 8;   // A: +8 rows for tiles 1,3
    const int cselA = (lane >> 4) & 1;         // A: +4 cols for tiles 2,3
    const int roffB = ((lane >> 4) & 1) * 8;   // B: +8 rows (nt+1) for tiles 2,3
    const int cselB = (lane >> 3) & 1;         // B: +4 cols for tiles 1,3
    const uint32_t aBase0 = sFb + (uint32_t)(32 * wy + roffA + l7) * 256;
    const uint32_t aBase1 = aBase0 + 16 * 256;
    const uint32_t bBase  = sWb + (uint32_t)(64 * wx + roffB + l7) * 256;

    float c[2][8][4];
    #pragma unroll
    for (int m = 0; m < 2; m++)
        #pragma unroll
        for (int n = 0; n < 8; n++)
            #pragma unroll
            for (int q = 0; q < 4; q++) c[m][n][q] = 0.f;

    #pragma unroll 1
    for (int ch = 0; ch < 6; ch++) {
        __syncthreads();    // previous chunk's consumers done

        // stage W chunk (coalesced copy from pre-transposed g_Wt, swizzled store)
        #pragma unroll
        for (int p = 0; p < 8; p++) {
            int idx = p * 256 + tid;              // 0..2047 float4s
            int j = idx >> 4, uu = idx & 15;
            float4 w = __ldg((const float4*)(g_Wt + (size_t)j * 384 + ch * 64) + uu);
            int u2 = uu ^ (j & 7);
            *(float4*)((char*)sW + j * 256 + u2 * 16) = w;
        }
        // stage feat chunk
        {
            const int sel  = ch >> 1;             // 0:zu 1:zv 2:|zu-zv|
            const int koff = (ch & 1) * 64 + half * 32;
            const float4* pu = (const float4*)(zu + koff);
            const float4* pv = (const float4*)(zv + koff);
            #pragma unroll
            for (int cc = 0; cc < 8; cc++) {
                int uu = half * 8 + cc;
                int u2 = uu ^ e7;
                float4 o;
                if (sel == 0)      o = tf4(__ldg(pu + cc));
                else if (sel == 1) o = tf4(__ldg(pv + cc));
                else {
                    float4 a = __ldg(pu + cc), b = __ldg(pv + cc);
                    float4 d;
                    d.x = fabsf(a.x - b.x); d.y = fabsf(a.y - b.y);
                    d.z = fabsf(a.z - b.z); d.w = fabsf(a.w - b.w);
                    o = tf4(d);
                }
                *(float4*)(fRow + u2 * 16) = o;
            }
        }
        __syncthreads();    // chunk staged

        // 8 k-steps of m16n8k8 over this 64-wide chunk
        #pragma unroll
        for (int ks = 0; ks < 8; ks++) {
            const uint32_t swzA = (uint32_t)(((ks * 2 + cselA) ^ l7)) << 4;
            const uint32_t swzB = (uint32_t)(((ks * 2 + cselB) ^ l7)) << 4;
            uint32_t a0[4], a1[4];
            ldsm4(a0[0], a0[1], a0[2], a0[3], aBase0 + swzA);
            ldsm4(a1[0], a1[1], a1[2], a1[3], aBase1 + swzA);
            #pragma unroll
            for (int g = 0; g < 4; g++) {
                uint32_t b[4];
                ldsm4(b[0], b[1], b[2], b[3], bBase + g * 4096 + swzB);
                mma_tf32(c[0][2*g  ][0], c[0][2*g  ][1], c[0][2*g  ][2], c[0][2*g  ][3],
                         a0[0], a0[1], a0[2], a0[3], b[0], b[1]);
                mma_tf32(c[0][2*g+1][0], c[0][2*g+1][1], c[0][2*g+1][2], c[0][2*g+1][3],
                         a0[0], a0[1], a0[2], a0[3], b[2], b[3]);
                mma_tf32(c[1][2*g  ][0], c[1][2*g  ][1], c[1][2*g  ][2], c[1][2*g  ][3],
                         a1[0], a1[1], a1[2], a1[3], b[0], b[1]);
                mma_tf32(c[1][2*g+1][0], c[1][2*g+1][1], c[1][2*g+1][2], c[1][2*g+1][3],
                         a1[0], a1[1], a1[2], a1[3], b[2], b[3]);
            }
        }
    }

    // epilogue: h = relu(C + b1); partial = h . W2; quad-shfl + smem reduce
    #pragma unroll
    for (int mt = 0; mt < 2; mt++) {
        float p1 = 0.f, p2 = 0.f;
        #pragma unroll
        for (int nt = 0; nt < 8; nt++) {
            int j = 64 * wx + 8 * nt + 2 * tig;
            float ba = sb1[j], bb = sb1[j + 1];
            float wa = sw2[j], wb = sw2[j + 1];
            p1 += fmaxf(c[mt][nt][0] + ba, 0.f) * wa + fmaxf(c[mt][nt][1] + bb, 0.f) * wb;
            p2 += fmaxf(c[mt][nt][2] + ba, 0.f) * wa + fmaxf(c[mt][nt][3] + bb, 0.f) * wb;
        }
        p1 += __shfl_xor_sync(0xFFFFFFFFu, p1, 1);
        p1 += __shfl_xor_sync(0xFFFFFFFFu, p1, 2);
        p2 += __shfl_xor_sync(0xFFFFFFFFu, p2, 1);
        p2 += __shfl_xor_sync(0xFFFFFFFFu, p2, 2);
        if (tig == 0) {
            int r = 32 * wy + 16 * mt + gid;
            sP[r * 2 + wx] = p1;
            sP[(r + 8) * 2 + wx] = p2;
        }
    }
    __syncthreads();

    if (tid < 128) {
        int ge = eBase + tid;
        if (ge < E) out[ge] = sP[tid * 2 + 0] + sP[tid * 2 + 1] + b2[0];
    }
}

extern "C" void kernel_launch(void* const* d_in, const int* in_sizes, int n_in,
                              void* d_out, int out_size) {
    const float* z    = (const float*)d_in[0];
    const int*   eidx = (const int*)d_in[1];   // int32 on the wire
    const float* W1   = (const float*)d_in[2];
    const float* b1   = (const float*)d_in[3];
    const float* W2   = (const float*)d_in[4];
    const float* b2   = (const float*)d_in[5];
    float*       out  = (float*)d_out;

    const int E = in_sizes[1] / 2;   // 500000

    const int smem = (128 * 64 * 2 + 256 + 128 + 128) * 4;   // 67584 B
    cudaFuncSetAttribute(edge_mlp_tc, cudaFuncAttributeMaxDynamicSharedMemorySize, smem);

    prep_wt<<<(384 * 128 + 255) / 256, 256>>>(W1);
    const int grid = (E + EPB - 1) / EPB;    // 3907
    edge_mlp_tc<<<grid, 256, smem>>>(z, eidx, b1, W2, b2, out, E);
}

// round 7
// speedup vs baseline: 2.5704x; 1.0369x over previous
#include <cuda_runtime.h>
#include <cstdint>

// MLPDecoder, split + tf32 mma.sync (base-ISA only; tcgen05 unavailable in this build).
// logit[e] = relu([zu,zv,|zu-zv|]@W1 + b1)@W2 + b2
//  prep:   g_Wab[j][k]=tf32(W1ab^T), g_Wc[j][k]=tf32(W1c^T)
//  k1:     AB[n][0:256] = [ z[n]@W1a , z[n]@W1b ]          (tensor, 128x256 tiles)
//  k2:     C = |zu-zv| @ W1c  (K=128, W1c smem-resident),
//          h = relu(C + ABu[j] + ABv[128+j] + b1), out = h@W2 + b2  (fused)
// edge_index is int32 on the wire (JAX x64 disabled).

#define DIM 128
#define NMAX 100000

__device__ float g_Wab[256 * 128];               // [j][k] tf32
__device__ float g_Wc[128 * 128];                // [j][k] tf32
__device__ float g_AB[(size_t)NMAX * 256];

__device__ __forceinline__ uint32_t f2tf(float x) {
    uint32_t r; asm("cvt.rna.tf32.f32 %0, %1;" : "=r"(r) : "f"(x)); return r;
}
__device__ __forceinline__ float tfpack(float x) { return __uint_as_float(f2tf(x)); }
__device__ __forceinline__ float4 tf4(float4 a) {
    float4 o; o.x = tfpack(a.x); o.y = tfpack(a.y); o.z = tfpack(a.z); o.w = tfpack(a.w);
    return o;
}
__device__ __forceinline__ void ldsm4(uint32_t& r0, uint32_t& r1, uint32_t& r2, uint32_t& r3,
                                      uint32_t addr) {
    asm volatile("ldmatrix.sync.aligned.m8n8.x4.shared.b16 {%0,%1,%2,%3}, [%4];"
                 : "=r"(r0), "=r"(r1), "=r"(r2), "=r"(r3) : "r"(addr));
}
__device__ __forceinline__ void mma_tf32(
    float& c0, float& c1, float& c2, float& c3,
    uint32_t a0, uint32_t a1, uint32_t a2, uint32_t a3,
    uint32_t b0, uint32_t b1)
{
    asm volatile(
        "mma.sync.aligned.m16n8k8.row.col.f32.tf32.tf32.f32 "
        "{%0,%1,%2,%3}, {%4,%5,%6,%7}, {%8,%9}, {%0,%1,%2,%3};"
        : "+f"(c0), "+f"(c1), "+f"(c2), "+f"(c3)
        : "r"(a0), "r"(a1), "r"(a2), "r"(a3), "r"(b0), "r"(b1));
}

// ---------------------------------------------------------------------------
__global__ void prep_w(const float* __restrict__ W1) {
    int i = blockIdx.x * 256 + threadIdx.x;
    if (i < 32768) {                       // Wab
        int j = i >> 7, k = i & 127;
        g_Wab[i] = tfpack(W1[(k + (j < 128 ? 0 : 128)) * 128 + (j & 127)]);
    } else if (i < 49152) {                // Wc
        int l = i - 32768;
        int j = l >> 7, k = l & 127;
        g_Wc[l] = tfpack(W1[(256 + k) * 128 + j]);
    }
}

// ---------------------------------------------------------------------------
// Kernel 1: AB = z @ [W1a|W1b].  Tile 128 rows x 256 cols, K=128.
// 512 threads, warp tile 32r x 64c. smem: sW [256j][128k] 131072B + sZ 2x16384B.
// ---------------------------------------------------------------------------
__global__ __launch_bounds__(512, 1) void ab_gemm(
    const float* __restrict__ z, float* __restrict__ AB, int N)
{
    extern __shared__ __align__(16) unsigned char smem[];
    float* sW = (float*)smem;                           // 256 x 128 (512B rows, swz)
    const int tid  = threadIdx.x;
    const int warp = tid >> 5;
    const int lane = tid & 31;
    const int wy = warp >> 2, wx = warp & 3;
    const int gid = lane >> 2, tig = lane & 3;
    const int rowBase = blockIdx.x * 128;

    // stage W (one-time): 8192 float4
    #pragma unroll
    for (int p = 0; p < 16; p++) {
        int i = p * 512 + tid;
        int j = i >> 5, uu = i & 31;
        float4 w = __ldg((const float4*)g_Wab + (size_t)j * 32 + uu);
        *(float4*)(smem + j * 512 + ((uu ^ (j & 7)) << 4)) = w;
    }

    const uint32_t sWb = (uint32_t)__cvta_generic_to_shared(sW);
    const uint32_t sZb = sWb + 131072;
    const int l7 = lane & 7;
    const int roffA = ((lane >> 3) & 1) * 8, cselA = (lane >> 4) & 1;
    const int roffB = ((lane >> 4) & 1) * 8, cselB = (lane >> 3) & 1;

    // z chunk staging: thread r = tid&127, h = tid>>7 -> k = 32c + 8h (2 float4)
    const int r_s = tid & 127;
    const int h_s = tid >> 7;
    const int zr  = (rowBase + r_s < N) ? rowBase + r_s : N - 1;
    const float* zrow = z + (size_t)zr * DIM + h_s * 8;
    const int e7 = r_s & 7;

    auto stageZ = [&](int c, int buf) {
        const float4* src = (const float4*)(zrow + c * 32);
        float4 a = __ldg(src), b = __ldg(src + 1);
        unsigned char* dst = smem + 131072 + buf * 16384 + r_s * 128;
        *(float4*)(dst + (((2 * h_s) ^ e7) << 4))     = tf4(a);
        *(float4*)(dst + (((2 * h_s + 1) ^ e7) << 4)) = tf4(b);
    };

    float c[2][8][4];
    #pragma unroll
    for (int m = 0; m < 2; m++)
        #pragma unroll
        for (int n = 0; n < 8; n++)
            #pragma unroll
            for (int q = 0; q < 4; q++) c[m][n][q] = 0.f;

    stageZ(0, 0);
    __syncthreads();

    #pragma unroll
    for (int ch = 0; ch < 4; ch++) {
        if (ch < 3) stageZ(ch + 1, (ch + 1) & 1);
        const uint32_t zbuf = sZb + (ch & 1) * 16384;
        #pragma unroll
        for (int ks = 0; ks < 4; ks++) {
            const int kk = ch * 4 + ks;
            const uint32_t swzA = (uint32_t)(((2 * ks + cselA) ^ l7)) << 4;
            const uint32_t swzB = (uint32_t)(((2 * kk + cselB) ^ l7)) << 4;
            uint32_t a[2][4];
            #pragma unroll
            for (int mt = 0; mt < 2; mt++)
                ldsm4(a[mt][0], a[mt][1], a[mt][2], a[mt][3],
                      zbuf + (uint32_t)(32 * wy + 16 * mt + roffA + l7) * 128 + swzA);
            #pragma unroll
            for (int g = 0; g < 4; g++) {
                uint32_t b[4];
                ldsm4(b[0], b[1], b[2], b[3],
                      sWb + (uint32_t)(64 * wx + 16 * g + roffB + l7) * 512 + swzB);
                #pragma unroll
                for (int mt = 0; mt < 2; mt++) {
                    mma_tf32(c[mt][2*g  ][0], c[mt][2*g  ][1], c[mt][2*g  ][2], c[mt][2*g  ][3],
                             a[mt][0], a[mt][1], a[mt][2], a[mt][3], b[0], b[1]);
                    mma_tf32(c[mt][2*g+1][0], c[mt][2*g+1][1], c[mt][2*g+1][2], c[mt][2*g+1][3],
                             a[mt][0], a[mt][1], a[mt][2], a[mt][3], b[2], b[3]);
                }
            }
        }
        __syncthreads();
    }

    // write AB (float2 per n8-tile per row)
    #pragma unroll
    for (int mt = 0; mt < 2; mt++) {
        int r0 = rowBase + 32 * wy + 16 * mt + gid;
        int r1 = r0 + 8;
        #pragma unroll
        for (int nt = 0; nt < 8; nt++) {
            int col = 64 * wx + 8 * nt + 2 * tig;
            if (r0 < N) *(float2*)(AB + (size_t)r0 * 256 + col) = make_float2(c[mt][nt][0], c[mt][nt][1]);
            if (r1 < N) *(float2*)(AB + (size_t)r1 * 256 + col) = make_float2(c[mt][nt][2], c[mt][nt][3]);
        }
    }
}

// ---------------------------------------------------------------------------
// Kernel 2: per 128-edge tile, C = diff @ W1c (K=128), fused epilogue.
// 512 threads, warp tile 32e x 32j. smem: sW 64K + sF 2x16K + sS[128][132] fp32.
// ---------------------------------------------------------------------------
#define SS_OFF   98304            // after sW(65536) + sF(32768)
#define SB1_OFF  165888           // after sS 67584
#define SW2_OFF  166400
#define SP_OFF   166912           // 128*4 floats
#define K2_SMEM  168960

__global__ __launch_bounds__(512, 1) void edge_mlp(
    const float* __restrict__ z, const int* __restrict__ eidx,
    const float* __restrict__ b1, const float* __restrict__ W2,
    const float* __restrict__ b2, const float* __restrict__ AB,
    float* __restrict__ out, int E)
{
    extern __shared__ __align__(16) unsigned char smem[];
    float* sS  = (float*)(smem + SS_OFF);     // [128e][132]
    float* sb1 = (float*)(smem + SB1_OFF);
    float* sw2 = (float*)(smem + SW2_OFF);
    float* sP  = (float*)(smem + SP_OFF);     // [128e][4]

    const int tid  = threadIdx.x;
    const int warp = tid >> 5;
    const int lane = tid & 31;
    const int wy = warp >> 2, wx = warp & 3;
    const int gid = lane >> 2, tig = lane & 3;
    const int eBase = blockIdx.x * 128;

    if (tid < 128) { sb1[tid] = b1[tid]; sw2[tid] = W2[tid]; }

    // stage W1c (one-time): 4096 float4
    #pragma unroll
    for (int p = 0; p < 8; p++) {
        int i = p * 512 + tid;
        int j = i >> 5, uu = i & 31;
        float4 w = __ldg((const float4*)g_Wc + (size_t)j * 32 + uu);
        *(float4*)(smem + j * 512 + ((uu ^ (j & 7)) << 4)) = w;
    }

    // edge assignment: e = tid&127, h = tid>>7
    const int e_s = tid & 127;
    const int h_s = tid >> 7;
    const int ge  = eBase + e_s;
    int u = 0, v = 0;
    if (ge < E) { u = eidx[ge]; v = eidx[E + ge]; }
    const float* zu = z + (size_t)u * DIM + h_s * 8;
    const float* zv = z + (size_t)v * DIM + h_s * 8;
    const int e7 = e_s & 7;

    // stage S = ABu[32h..] + ABv[128+32h..]  (8 float4 contiguous each)
    {
        const float4* au = (const float4*)(AB + (size_t)u * 256 + 32 * h_s);
        const float4* av = (const float4*)(AB + (size_t)v * 256 + 128 + 32 * h_s);
        float* dst = sS + e_s * 132 + 32 * h_s;
        #pragma unroll
        for (int q = 0; q < 8; q++) {
            float4 a = __ldg(au + q), b = __ldg(av + q);
            float4 s; s.x = a.x + b.x; s.y = a.y + b.y; s.z = a.z + b.z; s.w = a.w + b.w;
            *(float4*)(dst + q * 4) = s;
        }
    }

    auto stageF = [&](int c, int buf) {
        const float4* pu = (const float4*)(zu + c * 32);
        const float4* pv = (const float4*)(zv + c * 32);
        float4 a0 = __ldg(pu), b0 = __ldg(pv);
        float4 a1 = __ldg(pu + 1), b1v = __ldg(pv + 1);
        float4 d0, d1;
        d0.x = fabsf(a0.x - b0.x); d0.y = fabsf(a0.y - b0.y);
        d0.z = fabsf(a0.z - b0.z); d0.w = fabsf(a0.w - b0.w);
        d1.x = fabsf(a1.x - b1v.x); d1.y = fabsf(a1.y - b1v.y);
        d1.z = fabsf(a1.z - b1v.z); d1.w = fabsf(a1.w - b1v.w);
        unsigned char* dst = smem + 65536 + buf * 16384 + e_s * 128;
        *(float4*)(dst + (((2 * h_s) ^ e7) << 4))     = tf4(d0);
        *(float4*)(dst + (((2 * h_s + 1) ^ e7) << 4)) = tf4(d1);
    };

    const uint32_t sWb = (uint32_t)__cvta_generic_to_shared(smem);
    const uint32_t sFb = sWb + 65536;
    const int l7 = lane & 7;
    const int roffA = ((lane >> 3) & 1) * 8, cselA = (lane >> 4) & 1;
    const int roffB = ((lane >> 4) & 1) * 8, cselB = (lane >> 3) & 1;

    float c[2][4][4];
    #pragma unroll
    for (int m = 0; m < 2; m++)
        #pragma unroll
        for (int n = 0; n < 4; n++)
            #pragma unroll
            for (int q = 0; q < 4; q++) c[m][n][q] = 0.f;

    stageF(0, 0);
    __syncthreads();

    // preload b1/w2 pairs for this thread's j's
    float b1r[4][2], w2r[4][2];
    #pragma unroll
    for (int nt = 0; nt < 4; nt++) {
        int j = 32 * wx + 8 * nt + 2 * tig;
        b1r[nt][0] = sb1[j]; b1r[nt][1] = sb1[j + 1];
        w2r[nt][0] = sw2[j]; w2r[nt][1] = sw2[j + 1];
    }

    #pragma unroll
    for (int ch = 0; ch < 4; ch++) {
        if (ch < 3) stageF(ch + 1, (ch + 1) & 1);
        const uint32_t fbuf = sFb + (ch & 1) * 16384;
        #pragma unroll
        for (int ks = 0; ks < 4; ks++) {
            const int kk = ch * 4 + ks;
            const uint32_t swzA = (uint32_t)(((2 * ks + cselA) ^ l7)) << 4;
            const uint32_t swzB = (uint32_t)(((2 * kk + cselB) ^ l7)) << 4;
            uint32_t a[2][4];
            #pragma unroll
            for (int mt = 0; mt < 2; mt++)
                ldsm4(a[mt][0], a[mt][1], a[mt][2], a[mt][3],
                      fbuf + (uint32_t)(32 * wy + 16 * mt + roffA + l7) * 128 + swzA);
            #pragma unroll
            for (int g = 0; g < 2; g++) {
                uint32_t b[4];
                ldsm4(b[0], b[1], b[2], b[3],
                      sWb + (uint32_t)(32 * wx + 16 * g + roffB + l7) * 512 + swzB);
                #pragma unroll
                for (int mt = 0; mt < 2; mt++) {
                    mma_tf32(c[mt][2*g  ][0], c[mt][2*g  ][1], c[mt][2*g  ][2], c[mt][2*g  ][3],
                             a[mt][0], a[mt][1], a[mt][2], a[mt][3], b[0], b[1]);
                    mma_tf32(c[mt][2*g+1][0], c[mt][2*g+1][1], c[mt][2*g+1][2], c[mt][2*g+1][3],
                             a[mt][0], a[mt][1], a[mt][2], a[mt][3], b[2], b[3]);
                }
            }
        }
        __syncthreads();
    }

    // epilogue: per thread 4 edge-partials (mt x {gid, gid+8})
    float pe[2][2] = {{0.f, 0.f}, {0.f, 0.f}};
    #pragma unroll
    for (int mt = 0; mt < 2; mt++) {
        int e0 = 32 * wy + 16 * mt + gid;
        #pragma unroll
        for (int nt = 0; nt < 4; nt++) {
            int j = 32 * wx + 8 * nt + 2 * tig;
            const float* s0 = sS + e0 * 132 + j;
            const float* s1 = sS + (e0 + 8) * 132 + j;
            pe[mt][0] += fmaxf(c[mt][nt][0] + s0[0] + b1r[nt][0], 0.f) * w2r[nt][0]
                       + fmaxf(c[mt][nt][1] + s0[1] + b1r[nt][1], 0.f) * w2r[nt][1];
            pe[mt][1] += fmaxf(c[mt][nt][2] + s1[0] + b1r[nt][0], 0.f) * w2r[nt][0]
                       + fmaxf(c[mt][nt][3] + s1[1] + b1r[nt][1], 0.f) * w2r[nt][1];
        }
    }
    #pragma unroll
    for (int mt = 0; mt < 2; mt++)
        #pragma unroll
        for (int hh = 0; hh < 2; hh++) {
            float p = pe[mt][hh];
            p += __shfl_xor_sync(0xFFFFFFFFu, p, 1);
            p += __shfl_xor_sync(0xFFFFFFFFu, p, 2);
            if (tig == 0) sP[(32 * wy + 16 * mt + 8 * hh + gid) * 4 + wx] = p;
        }
    __syncthreads();

    if (tid < 128) {
        int g = eBase + tid;
        if (g < E)
            out[g] = sP[tid * 4] + sP[tid * 4 + 1] + sP[tid * 4 + 2] + sP[tid * 4 + 3] + b2[0];
    }
}

extern "C" void kernel_launch(void* const* d_in, const int* in_sizes, int n_in,
                              void* d_out, int out_size) {
    const float* z    = (const float*)d_in[0];
    const int*   eidx = (const int*)d_in[1];   // int32 on the wire
    const float* W1   = (const float*)d_in[2];
    const float* b1   = (const float*)d_in[3];
    const float* W2   = (const float*)d_in[4];
    const float* b2   = (const float*)d_in[5];
    float*       out  = (float*)d_out;

    const int N = in_sizes[0] / DIM;           // 100000
    const int E = in_sizes[1] / 2;             // 500000

    float* AB = nullptr;
    cudaGetSymbolAddress((void**)&AB, g_AB);

    const int k1_smem = 131072 + 32768;        // 163840
    cudaFuncSetAttribute(ab_gemm,  cudaFuncAttributeMaxDynamicSharedMemorySize, k1_smem);
    cudaFuncSetAttribute(edge_mlp, cudaFuncAttributeMaxDynamicSharedMemorySize, K2_SMEM);

    prep_w<<<192, 256>>>(W1);
    ab_gemm<<<(N + 127) / 128, 512, k1_smem>>>(z, AB, N);
    edge_mlp<<<(E + 127) / 128, 512, K2_SMEM>>>(z, eidx, b1, W2, b2, AB, out, E);
}